// round 4
// baseline (speedup 1.0000x reference)
#include <cuda_runtime.h>
#include <math.h>

#define S_LEN 2048
#define R_LEN 384
#define D_LEN 64

// attention output o (already softmax-normalized), per r: [R][64], j = h*8+c
__device__ float g_o[R_LEN * 64];

#define FMA2(d, a, b) asm("fma.rn.f32x2 %0, %1, %2, %0;" : "+l"(d) : "l"(a), "l"(b))
#define PACKDUP(d, x) asm("mov.b64 %0, {%1, %1};" : "=l"(d) : "r"(__float_as_uint(x)))
#define UNPACK2(lo, hi, v) asm("mov.b64 {%0, %1}, %2;" : "=r"(lo), "=r"(hi) : "l"(v))
#define PACK2(d, lo, hi) asm("mov.b64 %0, {%1, %2};" : "=l"(d) : "r"(__float_as_uint(lo)), "r"(__float_as_uint(hi)))

// Butterfly reduce-scatter: each lane holds v[32]; afterwards lane l holds
// sum over lanes of v_lane[l]. Destroys v. 31 shuffles.
__device__ __forceinline__ float bf_reduce32(float* v, int lane) {
#pragma unroll
    for (int m = 16; m >= 1; m >>= 1) {
        const bool hi = (lane & m) != 0;
#pragma unroll
        for (int i = 0; i < m; i++) {
            float send = hi ? v[i] : v[i + m];
            float recv = __shfl_xor_sync(0xffffffffu, send, m);
            float keep = hi ? v[i + m] : v[i];
            v[i] = keep + recv;
        }
    }
    return v[0];
}

// ---------------------------------------------------------------------------
// Kernel 1: one block per residue r. 512 threads (16 warps) for MLP.
// ---------------------------------------------------------------------------
#define NW 16
#define NTHR 512

extern __shared__ char smem_raw[];

__global__ void __launch_bounds__(NTHR, 1) attn_kernel(
    const float* __restrict__ M, const float* __restrict__ mask,
    const float* __restrict__ lng, const float* __restrict__ lnb,
    const float* __restrict__ Wq, const float* __restrict__ Wk,
    const float* __restrict__ Wv)
{
    float* kT    = (float*)smem_raw;          // [8][2048] -> later logits [8][2048]
    float* vT    = kT + 8 * S_LEN;            // [8][2048]
    float* bia   = vT + 8 * S_LEN;            // [2048]
    float* qws   = bia + S_LEN;               // [NW][64] warp partials (q, then o)
    float* wk_s  = qws + NW * 64;             // [64][8]
    float* wv_s  = wk_s + 512;                // [64][8]
    float* lng_s = wv_s + 512;                // 64
    float* lnb_s = lng_s + 64;                // 64
    float* q_s   = lnb_s + 64;                // 64
    float* qavg  = q_s + 64;                  // 64
    float* wred  = qavg + 64;                 // [NW][8]
    float* fmax_s = wred + NW * 8;            // 8
    float* fsum_s = fmax_s + 8;               // 8
    float* cred  = fsum_s + 8;                // NW

    const int tid = threadIdx.x;
    const int lane = tid & 31;
    const int w = tid >> 5;
    const int r = blockIdx.x;

    for (int i = tid; i < 512; i += NTHR) { wk_s[i] = Wk[i]; wv_s[i] = Wv[i]; }
    if (tid < 64) { lng_s[tid] = lng[tid]; lnb_s[tid] = lnb[tid]; }
    __syncthreads();

    float qa0 = 0.f, qa1 = 0.f, cntp = 0.f;

    // ---- pass A: LN, k, v, masked query accumulation -----------------------
    for (int it = 0; it < S_LEN / NTHR; it++) {
        const int s = it * NTHR + tid;
        const float4* row = (const float4*)(M + ((size_t)s * R_LEN + r) * 64);

        float sum = 0.f, sq = 0.f;
#pragma unroll
        for (int i = 0; i < 16; i++) {
            float4 t = row[i];
            sum += t.x + t.y + t.z + t.w;
            sq  += t.x * t.x + t.y * t.y + t.z * t.z + t.w * t.w;
        }
        const float mu = sum * (1.f / 64.f);
        const float var = sq * (1.f / 64.f) - mu * mu;
        const float rs = rsqrtf(var + 1e-5f);

        float kk[8], vv[8];
#pragma unroll
        for (int c = 0; c < 8; c++) { kk[c] = 0.f; vv[c] = 0.f; }
#pragma unroll 4
        for (int i = 0; i < 16; i++) {
            float4 t = row[i];
#pragma unroll
            for (int kq = 0; kq < 4; kq++) {
                const int d = 4 * i + kq;
                float val = (kq == 0) ? t.x : (kq == 1) ? t.y : (kq == 2) ? t.z : t.w;
                float nd = (val - mu) * rs * lng_s[d] + lnb_s[d];
                const float4* a = (const float4*)(wk_s + d * 8);
                const float4* b = (const float4*)(wv_s + d * 8);
                float4 a0 = a[0], a1 = a[1], b0 = b[0], b1 = b[1];
                kk[0] = fmaf(nd, a0.x, kk[0]); kk[1] = fmaf(nd, a0.y, kk[1]);
                kk[2] = fmaf(nd, a0.z, kk[2]); kk[3] = fmaf(nd, a0.w, kk[3]);
                kk[4] = fmaf(nd, a1.x, kk[4]); kk[5] = fmaf(nd, a1.y, kk[5]);
                kk[6] = fmaf(nd, a1.z, kk[6]); kk[7] = fmaf(nd, a1.w, kk[7]);
                vv[0] = fmaf(nd, b0.x, vv[0]); vv[1] = fmaf(nd, b0.y, vv[1]);
                vv[2] = fmaf(nd, b0.z, vv[2]); vv[3] = fmaf(nd, b0.w, vv[3]);
                vv[4] = fmaf(nd, b1.x, vv[4]); vv[5] = fmaf(nd, b1.y, vv[5]);
                vv[6] = fmaf(nd, b1.z, vv[6]); vv[7] = fmaf(nd, b1.w, vv[7]);
            }
        }
#pragma unroll
        for (int c = 0; c < 8; c++) { kT[c * S_LEN + s] = kk[c]; vT[c * S_LEN + s] = vv[c]; }

        const float mk = mask[(size_t)s * R_LEN + r];
        bia[s] = 1e9f * (mk - 1.f);
        cntp += mk;

#pragma unroll
        for (int hlf = 0; hlf < 2; hlf++) {
            float p[32];
#pragma unroll
            for (int i = 0; i < 8; i++) {
                float4 t = row[hlf * 8 + i];
                const int d = hlf * 32 + 4 * i;
                p[4 * i + 0] = mk * ((t.x - mu) * rs * lng_s[d + 0] + lnb_s[d + 0]);
                p[4 * i + 1] = mk * ((t.y - mu) * rs * lng_s[d + 1] + lnb_s[d + 1]);
                p[4 * i + 2] = mk * ((t.z - mu) * rs * lng_s[d + 2] + lnb_s[d + 2]);
                p[4 * i + 3] = mk * ((t.w - mu) * rs * lng_s[d + 3] + lnb_s[d + 3]);
            }
            float red = bf_reduce32(p, lane);
            if (hlf == 0) qa0 += red; else qa1 += red;
        }
    }

    qws[w * 64 + lane]      = qa0;
    qws[w * 64 + 32 + lane] = qa1;
    float cw = cntp;
#pragma unroll
    for (int o = 16; o >= 1; o >>= 1) cw += __shfl_xor_sync(0xffffffffu, cw, o);
    if (lane == 0) cred[w] = cw;
    __syncthreads();

    if (tid < 64) {
        float qs = 0.f;
#pragma unroll
        for (int ww = 0; ww < NW; ww++) qs += qws[ww * 64 + tid];
        float cnt = 0.f;
#pragma unroll
        for (int ww = 0; ww < NW; ww++) cnt += cred[ww];
        qavg[tid] = qs / (cnt + 1e-10f);
    }
    __syncthreads();
    if (tid < 64) {
        float a = 0.f;
#pragma unroll
        for (int d = 0; d < 64; d++) a = fmaf(qavg[d], Wq[d * 64 + tid], a);
        q_s[tid] = a * 0.35355339059327373f;
    }
    __syncthreads();

    // ---- pass B: logits + per-head max ------------------------------------
    float mx[8];
#pragma unroll
    for (int h = 0; h < 8; h++) mx[h] = -1e30f;
    for (int it = 0; it < S_LEN / NTHR; it++) {
        const int s = it * NTHR + tid;
        float kv[8];
#pragma unroll
        for (int c = 0; c < 8; c++) kv[c] = kT[c * S_LEN + s];
        const float b = bia[s];
#pragma unroll
        for (int h = 0; h < 8; h++) {
            float l = b;
#pragma unroll
            for (int c = 0; c < 8; c++) l = fmaf(q_s[h * 8 + c], kv[c], l);
            kT[h * S_LEN + s] = l;
            mx[h] = fmaxf(mx[h], l);
        }
    }
#pragma unroll
    for (int h = 0; h < 8; h++) {
#pragma unroll
        for (int o = 16; o >= 1; o >>= 1)
            mx[h] = fmaxf(mx[h], __shfl_xor_sync(0xffffffffu, mx[h], o));
    }
    if (lane == 0) {
#pragma unroll
        for (int h = 0; h < 8; h++) wred[w * 8 + h] = mx[h];
    }
    __syncthreads();
    if (tid < 8) {
        float m0 = wred[tid];
#pragma unroll
        for (int ww = 1; ww < NW; ww++) m0 = fmaxf(m0, wred[ww * 8 + tid]);
        fmax_s[tid] = m0;
    }
    __syncthreads();

    // ---- pass C: exp, sum, o accumulation ----------------------------------
    float fm[8];
#pragma unroll
    for (int h = 0; h < 8; h++) fm[h] = fmax_s[h];
    float sacc[8], oacc[64];
#pragma unroll
    for (int h = 0; h < 8; h++) sacc[h] = 0.f;
#pragma unroll
    for (int j = 0; j < 64; j++) oacc[j] = 0.f;

    for (int it = 0; it < S_LEN / NTHR; it++) {
        const int s = it * NTHR + tid;
        float e[8];
#pragma unroll
        for (int h = 0; h < 8; h++) {
            e[h] = __expf(kT[h * S_LEN + s] - fm[h]);
            sacc[h] += e[h];
        }
        float vv2[8];
#pragma unroll
        for (int c = 0; c < 8; c++) vv2[c] = vT[c * S_LEN + s];
#pragma unroll
        for (int h = 0; h < 8; h++)
#pragma unroll
            for (int c = 0; c < 8; c++)
                oacc[h * 8 + c] = fmaf(e[h], vv2[c], oacc[h * 8 + c]);
    }
#pragma unroll
    for (int h = 0; h < 8; h++) {
#pragma unroll
        for (int o = 16; o >= 1; o >>= 1)
            sacc[h] += __shfl_xor_sync(0xffffffffu, sacc[h], o);
    }
    if (lane == 0) {
#pragma unroll
        for (int h = 0; h < 8; h++) wred[w * 8 + h] = sacc[h];
    }
    float o0 = bf_reduce32(oacc, lane);
    float o1 = bf_reduce32(oacc + 32, lane);
    qws[w * 64 + lane] = o0;
    qws[w * 64 + 32 + lane] = o1;
    __syncthreads();
    if (tid < 8) {
        float ss = 0.f;
#pragma unroll
        for (int ww = 0; ww < NW; ww++) ss += wred[ww * 8 + tid];
        fsum_s[tid] = ss;
    }
    __syncthreads();
    if (tid < 64) {
        float t = 0.f;
#pragma unroll
        for (int ww = 0; ww < NW; ww++) t += qws[ww * 64 + tid];
        g_o[r * 64 + tid] = t / fsum_s[tid >> 3];
    }
}

// ---------------------------------------------------------------------------
// Kernel 2: block = 128 consecutive r at fixed s, fully coalesced global I/O.
// ---------------------------------------------------------------------------
#define NT_STRIDE 132
#define MS_STRIDE 68

__global__ void __launch_bounds__(256) out_kernel(
    const float* __restrict__ M,
    const float* __restrict__ lng, const float* __restrict__ lnb,
    const float* __restrict__ Wg, const float* __restrict__ bg,
    const float* __restrict__ Wo, const float* __restrict__ bo,
    float* __restrict__ out)
{
    extern __shared__ float sm[];
    float* Ms    = sm;                    // [128][68] raw M tile (kept for residual)
    float* Nt    = Ms + 128 * MS_STRIDE;  // [64][132] normalized^T / Gt / Rs[128][68]
    float* wg_s  = Nt + 128 * MS_STRIDE;  // 4096 (Nt region sized 128*68 >= 64*132)
    float* wo_s  = wg_s + 4096;           // 4096
    float* lng_s = wo_s + 4096;           // 64
    float* lnb_s = lng_s + 64;            // 64
    float* bg_s  = lnb_s + 64;            // 64
    float* bo_s  = bg_s + 64;             // 64

    const int tid = threadIdx.x;
    const int r0 = blockIdx.x * 128;
    const int s  = blockIdx.y;
    const float* gbase = M + ((size_t)s * R_LEN + r0) * 64;

    for (int i = tid; i < 4096; i += 256) { wg_s[i] = Wg[i]; wo_s[i] = Wo[i]; }
    if (tid < 64) {
        lng_s[tid] = lng[tid]; lnb_s[tid] = lnb[tid];
        bg_s[tid] = bg[tid];   bo_s[tid] = bo[tid];
    }

    // ---- phase 1: coalesced tile copy to smem -----------------------------
    {
        const float4* g4 = (const float4*)gbase;
#pragma unroll
        for (int i = 0; i < 8; i++) {
            int idx = tid + i * 256;             // float4 index, 0..2047
            float4 v = g4[idx];
            int row = idx >> 4, c4 = idx & 15;
            *(float4*)(Ms + row * MS_STRIDE + c4 * 4) = v;
        }
    }
    __syncthreads();

    // ---- phase 2: LN stats (2 threads/row) + normalized transpose ----------
    {
        const int row = tid >> 1;
        const int hf  = tid & 1;
        float4 rv[8];
        const float4* src = (const float4*)(Ms + row * MS_STRIDE + hf * 32);
        float sum = 0.f, sq = 0.f;
#pragma unroll
        for (int i = 0; i < 8; i++) {
            float4 t = src[i];
            rv[i] = t;
            sum += t.x + t.y + t.z + t.w;
            sq  += t.x * t.x + t.y * t.y + t.z * t.z + t.w * t.w;
        }
        sum += __shfl_xor_sync(0xffffffffu, sum, 1);
        sq  += __shfl_xor_sync(0xffffffffu, sq, 1);
        const float mu = sum * (1.f / 64.f);
        const float rs = rsqrtf(sq * (1.f / 64.f) - mu * mu + 1e-5f);
#pragma unroll
        for (int i = 0; i < 8; i++) {
            float4 t = rv[i];
            const int d = hf * 32 + 4 * i;
            Nt[(d + 0) * NT_STRIDE + row] = (t.x - mu) * rs * lng_s[d + 0] + lnb_s[d + 0];
            Nt[(d + 1) * NT_STRIDE + row] = (t.y - mu) * rs * lng_s[d + 1] + lnb_s[d + 1];
            Nt[(d + 2) * NT_STRIDE + row] = (t.z - mu) * rs * lng_s[d + 2] + lnb_s[d + 2];
            Nt[(d + 3) * NT_STRIDE + row] = (t.w - mu) * rs * lng_s[d + 3] + lnb_s[d + 3];
        }
    }
    __syncthreads();

    const int rg = tid >> 4;   // rows rg*8 .. rg*8+7
    const int cg = tid & 15;   // cols cg*4 .. cg*4+3

    unsigned long long acc[4][4];
#pragma unroll
    for (int p = 0; p < 4; p++)
#pragma unroll
        for (int c = 0; c < 4; c++) acc[p][c] = 0ull;

    // ---- GEMM1: X = N @ Wg -------------------------------------------------
#pragma unroll 16
    for (int k = 0; k < 64; k++) {
        const ulonglong2* ap = (const ulonglong2*)(Nt + k * NT_STRIDE + rg * 8);
        ulonglong2 A01 = ap[0];
        ulonglong2 A23 = ap[1];
        unsigned long long a[4] = {A01.x, A01.y, A23.x, A23.y};
        float4 bw = *(const float4*)(wg_s + k * 64 + cg * 4);
        unsigned long long b[4];
        PACKDUP(b[0], bw.x); PACKDUP(b[1], bw.y);
        PACKDUP(b[2], bw.z); PACKDUP(b[3], bw.w);
#pragma unroll
        for (int p = 0; p < 4; p++)
#pragma unroll
            for (int c = 0; c < 4; c++) FMA2(acc[p][c], a[p], b[c]);
    }

    // ---- gate: g = sigmoid(x + bg) * o ------------------------------------
    unsigned long long gpk[4][4];
#pragma unroll
    for (int p = 0; p < 4; p++) {
        const int rA = rg * 8 + 2 * p;
        float4 oA = *(const float4*)(g_o + (size_t)(r0 + rA) * 64 + cg * 4);
        float4 oB = *(const float4*)(g_o + (size_t)(r0 + rA + 1) * 64 + cg * 4);
#pragma unroll
        for (int c = 0; c < 4; c++) {
            unsigned int ulo, uhi;
            UNPACK2(ulo, uhi, acc[p][c]);
            float xb = bg_s[cg * 4 + c];
            float xa = __uint_as_float(ulo) + xb;
            float xbv = __uint_as_float(uhi) + xb;
            float ga = __fdividef(1.f, 1.f + __expf(-xa));
            float gb = __fdividef(1.f, 1.f + __expf(-xbv));
            float ov_a = (c == 0) ? oA.x : (c == 1) ? oA.y : (c == 2) ? oA.z : oA.w;
            float ov_b = (c == 0) ? oB.x : (c == 1) ? oB.y : (c == 2) ? oB.z : oB.w;
            PACK2(gpk[p][c], ga * ov_a, gb * ov_b);
        }
    }
    __syncthreads();   // everyone done reading Nt

    // store G transposed into Nt (now Gt[j][row])
#pragma unroll
    for (int c = 0; c < 4; c++) {
        const int j = cg * 4 + c;
#pragma unroll
        for (int p = 0; p < 4; p++) {
            *(unsigned long long*)(Nt + j * NT_STRIDE + rg * 8 + 2 * p) = gpk[p][c];
        }
    }
    __syncthreads();

    // ---- GEMM2: OUT = G @ Wo ----------------------------------------------
#pragma unroll
    for (int p = 0; p < 4; p++)
#pragma unroll
        for (int c = 0; c < 4; c++) acc[p][c] = 0ull;

#pragma unroll 16
    for (int k = 0; k < 64; k++) {
        const ulonglong2* ap = (const ulonglong2*)(Nt + k * NT_STRIDE + rg * 8);
        ulonglong2 A01 = ap[0];
        ulonglong2 A23 = ap[1];
        unsigned long long a[4] = {A01.x, A01.y, A23.x, A23.y};
        float4 bw = *(const float4*)(wo_s + k * 64 + cg * 4);
        unsigned long long b[4];
        PACKDUP(b[0], bw.x); PACKDUP(b[1], bw.y);
        PACKDUP(b[2], bw.z); PACKDUP(b[3], bw.w);
#pragma unroll
        for (int p = 0; p < 4; p++)
#pragma unroll
            for (int c = 0; c < 4; c++) FMA2(acc[p][c], a[p], b[c]);
    }
    __syncthreads();   // done reading Gt; Nt region becomes Rs[128][68]

    // ---- stage results to smem row-major ----------------------------------
    float* Rs = Nt;
#pragma unroll
    for (int p = 0; p < 4; p++) {
        const int rA = rg * 8 + 2 * p;
        unsigned int lo0, hi0, lo1, hi1, lo2, hi2, lo3, hi3;
        UNPACK2(lo0, hi0, acc[p][0]);
        UNPACK2(lo1, hi1, acc[p][1]);
        UNPACK2(lo2, hi2, acc[p][2]);
        UNPACK2(lo3, hi3, acc[p][3]);
        *(float4*)(Rs + rA * MS_STRIDE + cg * 4) =
            make_float4(__uint_as_float(lo0), __uint_as_float(lo1),
                        __uint_as_float(lo2), __uint_as_float(lo3));
        *(float4*)(Rs + (rA + 1) * MS_STRIDE + cg * 4) =
            make_float4(__uint_as_float(hi0), __uint_as_float(hi1),
                        __uint_as_float(hi2), __uint_as_float(hi3));
    }
    __syncthreads();

    // ---- coalesced epilogue: out = M_raw + R + bo --------------------------
    {
        float4* o4 = (float4*)(out + ((size_t)s * R_LEN + r0) * 64);
#pragma unroll
        for (int i = 0; i < 8; i++) {
            int idx = tid + i * 256;
            int row = idx >> 4, c4 = idx & 15;
            float4 mr = *(const float4*)(Ms + row * MS_STRIDE + c4 * 4);
            float4 rr = *(const float4*)(Rs + row * MS_STRIDE + c4 * 4);
            float4 bb = *(const float4*)(bo_s + c4 * 4);
            o4[idx] = make_float4(mr.x + rr.x + bb.x, mr.y + rr.y + bb.y,
                                  mr.z + rr.z + bb.z, mr.w + rr.w + bb.w);
        }
    }
}

// ---------------------------------------------------------------------------
extern "C" void kernel_launch(void* const* d_in, const int* in_sizes, int n_in,
                              void* d_out, int out_size)
{
    const float* M    = (const float*)d_in[0];
    const float* mask = (const float*)d_in[1];
    const float* lng  = (const float*)d_in[2];
    const float* lnb  = (const float*)d_in[3];
    const float* Wq   = (const float*)d_in[4];
    const float* Wk   = (const float*)d_in[5];
    const float* Wv   = (const float*)d_in[6];
    const float* Wg   = (const float*)d_in[7];
    const float* bg   = (const float*)d_in[8];
    const float* Wo   = (const float*)d_in[9];
    const float* bo   = (const float*)d_in[10];
    float* out = (float*)d_out;

    const size_t smem1 = (size_t)(16384 + 16384 + 2048 + NW * 64 + 512 + 512 +
                                  64 + 64 + 64 + 64 + NW * 8 + 8 + 8 + NW) * sizeof(float);
    cudaFuncSetAttribute(attn_kernel, cudaFuncAttributeMaxDynamicSharedMemorySize,
                         (int)smem1);

    const size_t smem2 = (size_t)(128 * MS_STRIDE * 2 + 4096 + 4096 +
                                  4 * 64) * sizeof(float);
    cudaFuncSetAttribute(out_kernel, cudaFuncAttributeMaxDynamicSharedMemorySize,
                         (int)smem2);

    attn_kernel<<<R_LEN, NTHR, smem1>>>(M, mask, lng, lnb, Wq, Wk, Wv);
    out_kernel<<<dim3(R_LEN / 128, S_LEN), 256, smem2>>>(M, lng, lnb, Wg, bg, Wo, bo, out);
}

// round 8
// speedup vs baseline: 1.0182x; 1.0182x over previous
#include <cuda_runtime.h>
#include <math.h>

#define S_LEN 2048
#define R_LEN 384
#define D_LEN 64

// attention output o (already softmax-normalized), per r: [R][64], j = h*8+c
__device__ float g_o[R_LEN * 64];

#define FMA2(d, a, b) asm("fma.rn.f32x2 %0, %1, %2, %0;" : "+l"(d) : "l"(a), "l"(b))
#define PACKDUP(d, x) asm("mov.b64 %0, {%1, %1};" : "=l"(d) : "r"(__float_as_uint(x)))
#define UNPACK2(lo, hi, v) asm("mov.b64 {%0, %1}, %2;" : "=r"(lo), "=r"(hi) : "l"(v))
#define PACK2(d, lo, hi) asm("mov.b64 %0, {%1, %2};" : "=l"(d) : "r"(__float_as_uint(lo)), "r"(__float_as_uint(hi)))

// Butterfly reduce-scatter over 32 lanes: v[32] per lane -> lane l holds sum of v[l].
__device__ __forceinline__ float bf_reduce32(float* v, int lane) {
#pragma unroll
    for (int m = 16; m >= 1; m >>= 1) {
        const bool hi = (lane & m) != 0;
#pragma unroll
        for (int i = 0; i < m; i++) {
            float send = hi ? v[i] : v[i + m];
            float recv = __shfl_xor_sync(0xffffffffu, send, m);
            float keep = hi ? v[i + m] : v[i];
            v[i] = keep + recv;
        }
    }
    return v[0];
}

// ---------------------------------------------------------------------------
// Kernel 1: one block per residue r. 512 threads. Pass A is warp-cooperative:
// 16 lanes per row -> fully coalesced global loads.
// ---------------------------------------------------------------------------
#define NW 16
#define NTHR 512
#define KSTR 2050

extern __shared__ char smem_raw[];

__global__ void __launch_bounds__(NTHR, 1) attn_kernel(
    const float* __restrict__ M, const float* __restrict__ mask,
    const float* __restrict__ lng, const float* __restrict__ lnb,
    const float* __restrict__ Wq, const float* __restrict__ Wk,
    const float* __restrict__ Wv)
{
    float* kT    = (float*)smem_raw;          // [8][KSTR] -> later logits
    float* vT    = kT + 8 * KSTR;             // [8][KSTR]
    float* bia   = vT + 8 * KSTR;             // [2048]
    float* qws   = bia + S_LEN;               // [NW][128]
    float* q_s   = qws + NW * 128;            // 64
    float* qavg  = q_s + 64;                  // 64
    float* wred  = qavg + 64;                 // [NW][8]
    float* fmax_s = wred + NW * 8;            // 8
    float* fsum_s = fmax_s + 8;               // 8
    float* cred  = fsum_s + 8;                // NW

    const int tid  = threadIdx.x;
    const int lane = tid & 31;
    const int w    = tid >> 5;
    const int sub  = lane & 15;
    const int half = lane >> 4;
    const int r    = blockIdx.x;

    // Per-lane register preload: this lane owns dims d = sub*4 .. sub*4+3
    float wkr[4][8], wvr[4][8], lgr[4], lbr[4];
#pragma unroll
    for (int j = 0; j < 4; j++) {
        const int d = sub * 4 + j;
        lgr[j] = lng[d]; lbr[j] = lnb[d];
        const float4* wk4 = (const float4*)(Wk + d * 8);
        const float4* wv4 = (const float4*)(Wv + d * 8);
        float4 a0 = wk4[0], a1 = wk4[1], b0 = wv4[0], b1 = wv4[1];
        wkr[j][0] = a0.x; wkr[j][1] = a0.y; wkr[j][2] = a0.z; wkr[j][3] = a0.w;
        wkr[j][4] = a1.x; wkr[j][5] = a1.y; wkr[j][6] = a1.z; wkr[j][7] = a1.w;
        wvr[j][0] = b0.x; wvr[j][1] = b0.y; wvr[j][2] = b0.z; wvr[j][3] = b0.w;
        wvr[j][4] = b1.x; wvr[j][5] = b1.y; wvr[j][6] = b1.z; wvr[j][7] = b1.w;
    }

    float qa[4] = {0.f, 0.f, 0.f, 0.f};
    float cntp = 0.f;

    // ---- pass A: coalesced LN + k/v + masked query accumulation ------------
    for (int it = 0; it < 64; it++) {
        const int s = it * 32 + (w << 1) + half;
        const float4 t = *(const float4*)(M + ((size_t)s * R_LEN + r) * 64 + sub * 4);

        float sum = t.x + t.y + t.z + t.w;
        float sq  = t.x * t.x + t.y * t.y + t.z * t.z + t.w * t.w;
#pragma unroll
        for (int m = 1; m <= 8; m <<= 1) {
            sum += __shfl_xor_sync(0xffffffffu, sum, m);
            sq  += __shfl_xor_sync(0xffffffffu, sq, m);
        }
        const float mu = sum * (1.f / 64.f);
        const float rs = rsqrtf(sq * (1.f / 64.f) - mu * mu + 1e-5f);

        float nd[4];
        nd[0] = (t.x - mu) * rs * lgr[0] + lbr[0];
        nd[1] = (t.y - mu) * rs * lgr[1] + lbr[1];
        nd[2] = (t.z - mu) * rs * lgr[2] + lbr[2];
        nd[3] = (t.w - mu) * rs * lgr[3] + lbr[3];

        const float mk = __ldg(mask + (size_t)s * R_LEN + r);
        if (sub == 0) bia[s] = 1e9f * (mk - 1.f);
        cntp += mk;
#pragma unroll
        for (int j = 0; j < 4; j++) qa[j] += mk * nd[j];

        float red[16];
#pragma unroll
        for (int c = 0; c < 8; c++) {
            red[c] = nd[0] * wkr[0][c] + nd[1] * wkr[1][c] +
                     nd[2] * wkr[2][c] + nd[3] * wkr[3][c];
            red[8 + c] = nd[0] * wvr[0][c] + nd[1] * wvr[1][c] +
                         nd[2] * wvr[2][c] + nd[3] * wvr[3][c];
        }
        // reduce-scatter over the 16-lane group: lane 'sub' ends with red[sub]
#pragma unroll
        for (int m = 8; m >= 1; m >>= 1) {
            const bool hi = (sub & m) != 0;
#pragma unroll
            for (int i = 0; i < m; i++) {
                float send = hi ? red[i] : red[i + m];
                float recv = __shfl_xor_sync(0xffffffffu, send, m);
                float keep = hi ? red[i + m] : red[i];
                red[i] = keep + recv;
            }
        }
        if (sub < 8) kT[sub * KSTR + s] = red[0];
        else         vT[(sub - 8) * KSTR + s] = red[0];
    }

#pragma unroll
    for (int j = 0; j < 4; j++) qws[w * 128 + half * 64 + sub * 4 + j] = qa[j];
    float cw = cntp;
#pragma unroll
    for (int o = 16; o >= 1; o >>= 1) cw += __shfl_xor_sync(0xffffffffu, cw, o);
    if (lane == 0) cred[w] = cw;   // = 16 * (sum of mask over this warp's rows)
    __syncthreads();

    if (tid < 64) {
        float qs = 0.f;
#pragma unroll
        for (int ww = 0; ww < NW; ww++)
            qs += qws[ww * 128 + tid] + qws[ww * 128 + 64 + tid];
        float cnt = 0.f;
#pragma unroll
        for (int ww = 0; ww < NW; ww++) cnt += cred[ww];
        cnt *= (1.f / 16.f);
        qavg[tid] = qs / (cnt + 1e-10f);
    }
    __syncthreads();
    if (tid < 64) {
        float a = 0.f;
#pragma unroll
        for (int d = 0; d < 64; d++) a = fmaf(qavg[d], Wq[d * 64 + tid], a);
        q_s[tid] = a * 0.35355339059327373f;
    }
    __syncthreads();

    // ---- pass B: logits + per-head max ------------------------------------
    float mx[8];
#pragma unroll
    for (int h = 0; h < 8; h++) mx[h] = -1e30f;
    for (int it = 0; it < S_LEN / NTHR; it++) {
        const int s = it * NTHR + tid;
        float kv[8];
#pragma unroll
        for (int c = 0; c < 8; c++) kv[c] = kT[c * KSTR + s];
        const float b = bia[s];
#pragma unroll
        for (int h = 0; h < 8; h++) {
            float l = b;
#pragma unroll
            for (int c = 0; c < 8; c++) l = fmaf(q_s[h * 8 + c], kv[c], l);
            kT[h * KSTR + s] = l;
            mx[h] = fmaxf(mx[h], l);
        }
    }
#pragma unroll
    for (int h = 0; h < 8; h++) {
#pragma unroll
        for (int o = 16; o >= 1; o >>= 1)
            mx[h] = fmaxf(mx[h], __shfl_xor_sync(0xffffffffu, mx[h], o));
    }
    if (lane == 0) {
#pragma unroll
        for (int h = 0; h < 8; h++) wred[w * 8 + h] = mx[h];
    }
    __syncthreads();
    if (tid < 8) {
        float m0 = wred[tid];
#pragma unroll
        for (int ww = 1; ww < NW; ww++) m0 = fmaxf(m0, wred[ww * 8 + tid]);
        fmax_s[tid] = m0;
    }
    __syncthreads();

    // ---- pass C: exp, sum, o accumulation ----------------------------------
    float fm[8];
#pragma unroll
    for (int h = 0; h < 8; h++) fm[h] = fmax_s[h];
    float sacc[8], oacc[64];
#pragma unroll
    for (int h = 0; h < 8; h++) sacc[h] = 0.f;
#pragma unroll
    for (int j = 0; j < 64; j++) oacc[j] = 0.f;

    for (int it = 0; it < S_LEN / NTHR; it++) {
        const int s = it * NTHR + tid;
        float e[8];
#pragma unroll
        for (int h = 0; h < 8; h++) {
            e[h] = __expf(kT[h * KSTR + s] - fm[h]);
            sacc[h] += e[h];
        }
        float vv2[8];
#pragma unroll
        for (int c = 0; c < 8; c++) vv2[c] = vT[c * KSTR + s];
#pragma unroll
        for (int h = 0; h < 8; h++)
#pragma unroll
            for (int c = 0; c < 8; c++)
                oacc[h * 8 + c] = fmaf(e[h], vv2[c], oacc[h * 8 + c]);
    }
#pragma unroll
    for (int h = 0; h < 8; h++) {
#pragma unroll
        for (int o = 16; o >= 1; o >>= 1)
            sacc[h] += __shfl_xor_sync(0xffffffffu, sacc[h], o);
    }
    if (lane == 0) {
#pragma unroll
        for (int h = 0; h < 8; h++) wred[w * 8 + h] = sacc[h];
    }
    float o0 = bf_reduce32(oacc, lane);
    float o1 = bf_reduce32(oacc + 32, lane);
    qws[w * 128 + lane] = o0;
    qws[w * 128 + 32 + lane] = o1;
    __syncthreads();
    if (tid < 8) {
        float ss = 0.f;
#pragma unroll
        for (int ww = 0; ww < NW; ww++) ss += wred[ww * 8 + tid];
        fsum_s[tid] = ss;
    }
    __syncthreads();
    if (tid < 64) {
        float t = 0.f;
#pragma unroll
        for (int ww = 0; ww < NW; ww++) t += qws[ww * 128 + tid];
        g_o[r * 64 + tid] = t / fsum_s[tid >> 3];
    }
}

// ---------------------------------------------------------------------------
// Kernel 2: 128 r-rows at fixed s. Coalesced global I/O, 8x4 FFMA2 GEMMs,
// staged epilogue, 3 CTAs/SM.
// ---------------------------------------------------------------------------
#define NT_STRIDE 132
#define RS_STRIDE 68

__global__ void __launch_bounds__(256) out_kernel(
    const float* __restrict__ M,
    const float* __restrict__ lng, const float* __restrict__ lnb,
    const float* __restrict__ Wg, const float* __restrict__ bg,
    const float* __restrict__ Wo, const float* __restrict__ bo,
    float* __restrict__ out)
{
    extern __shared__ float sm[];
    float* NtRs  = sm;                 // 8704 floats: Nt[64][132] / Gt / Rs[128][68]
    float* wg_s  = NtRs + 8704;        // 4096
    float* wo_s  = wg_s + 4096;        // 4096
    float* lng_s = wo_s + 4096;        // 64
    float* lnb_s = lng_s + 64;         // 64
    float* bg_s  = lnb_s + 64;         // 64
    float* bo_s  = bg_s + 64;          // 64

    const int tid = threadIdx.x;
    const int r0 = blockIdx.x * 128;
    const int s  = blockIdx.y;
    const float* gbase = M + ((size_t)s * R_LEN + r0) * 64;

    for (int i = tid; i < 4096; i += 256) { wg_s[i] = Wg[i]; wo_s[i] = Wo[i]; }
    if (tid < 64) {
        lng_s[tid] = lng[tid]; lnb_s[tid] = lnb[tid];
        bg_s[tid] = bg[tid];   bo_s[tid] = bo[tid];
    }
    __syncthreads();   // lng_s/lnb_s needed below

    // ---- phase 1: coalesced load, shfl LN stats, transposed store ----------
    // thread holds column block c4 = tid&15 of rows (tid>>4)+16i, i=0..7
    {
        const int c4 = tid & 15;
        const float4* g4 = (const float4*)gbase;
        float4 rv[8];
        float s_[8], q_[8];
#pragma unroll
        for (int i = 0; i < 8; i++) {
            rv[i] = g4[tid + i * 256];
            s_[i] = rv[i].x + rv[i].y + rv[i].z + rv[i].w;
            q_[i] = rv[i].x * rv[i].x + rv[i].y * rv[i].y +
                    rv[i].z * rv[i].z + rv[i].w * rv[i].w;
        }
#pragma unroll
        for (int m = 1; m <= 8; m <<= 1) {
#pragma unroll
            for (int i = 0; i < 8; i++) {
                s_[i] += __shfl_xor_sync(0xffffffffu, s_[i], m);
                q_[i] += __shfl_xor_sync(0xffffffffu, q_[i], m);
            }
        }
        const float g0 = lng_s[4 * c4 + 0], g1 = lng_s[4 * c4 + 1];
        const float g2 = lng_s[4 * c4 + 2], g3 = lng_s[4 * c4 + 3];
        const float b0 = lnb_s[4 * c4 + 0], b1 = lnb_s[4 * c4 + 1];
        const float b2 = lnb_s[4 * c4 + 2], b3 = lnb_s[4 * c4 + 3];
#pragma unroll
        for (int i = 0; i < 8; i++) {
            const int row = (tid >> 4) + 16 * i;
            const float mu = s_[i] * (1.f / 64.f);
            const float rs = rsqrtf(q_[i] * (1.f / 64.f) - mu * mu + 1e-5f);
            NtRs[(4 * c4 + 0) * NT_STRIDE + row] = (rv[i].x - mu) * rs * g0 + b0;
            NtRs[(4 * c4 + 1) * NT_STRIDE + row] = (rv[i].y - mu) * rs * g1 + b1;
            NtRs[(4 * c4 + 2) * NT_STRIDE + row] = (rv[i].z - mu) * rs * g2 + b2;
            NtRs[(4 * c4 + 3) * NT_STRIDE + row] = (rv[i].w - mu) * rs * g3 + b3;
        }
    }
    __syncthreads();

    const int rg = tid >> 4;   // rows rg*8 .. rg*8+7
    const int cg = tid & 15;   // cols cg*4 .. cg*4+3

    unsigned long long acc[4][4];
#pragma unroll
    for (int p = 0; p < 4; p++)
#pragma unroll
        for (int c = 0; c < 4; c++) acc[p][c] = 0ull;

    // ---- GEMM1: X = N @ Wg -------------------------------------------------
#pragma unroll 16
    for (int k = 0; k < 64; k++) {
        const ulonglong2* ap = (const ulonglong2*)(NtRs + k * NT_STRIDE + rg * 8);
        ulonglong2 A01 = ap[0];
        ulonglong2 A23 = ap[1];
        unsigned long long a[4] = {A01.x, A01.y, A23.x, A23.y};
        float4 bw = *(const float4*)(wg_s + k * 64 + cg * 4);
        unsigned long long b[4];
        PACKDUP(b[0], bw.x); PACKDUP(b[1], bw.y);
        PACKDUP(b[2], bw.z); PACKDUP(b[3], bw.w);
#pragma unroll
        for (int p = 0; p < 4; p++)
#pragma unroll
            for (int c = 0; c < 4; c++) FMA2(acc[p][c], a[p], b[c]);
    }

    // ---- gate: g = sigmoid(x + bg) * o ------------------------------------
    unsigned long long gpk[4][4];
#pragma unroll
    for (int p = 0; p < 4; p++) {
        const int rA = rg * 8 + 2 * p;
        float4 oA = *(const float4*)(g_o + (size_t)(r0 + rA) * 64 + cg * 4);
        float4 oB = *(const float4*)(g_o + (size_t)(r0 + rA + 1) * 64 + cg * 4);
#pragma unroll
        for (int c = 0; c < 4; c++) {
            unsigned int ulo, uhi;
            UNPACK2(ulo, uhi, acc[p][c]);
            float xb = bg_s[cg * 4 + c];
            float xa = __uint_as_float(ulo) + xb;
            float xbv = __uint_as_float(uhi) + xb;
            float ga = __fdividef(1.f, 1.f + __expf(-xa));
            float gb = __fdividef(1.f, 1.f + __expf(-xbv));
            float ov_a = (c == 0) ? oA.x : (c == 1) ? oA.y : (c == 2) ? oA.z : oA.w;
            float ov_b = (c == 0) ? oB.x : (c == 1) ? oB.y : (c == 2) ? oB.z : oB.w;
            PACK2(gpk[p][c], ga * ov_a, gb * ov_b);
        }
    }
    __syncthreads();   // everyone done reading Nt

    // store G transposed (Gt[j][row])
#pragma unroll
    for (int c = 0; c < 4; c++) {
        const int j = cg * 4 + c;
#pragma unroll
        for (int p = 0; p < 4; p++) {
            *(unsigned long long*)(NtRs + j * NT_STRIDE + rg * 8 + 2 * p) = gpk[p][c];
        }
    }
    __syncthreads();

    // ---- GEMM2: OUT = G @ Wo ----------------------------------------------
#pragma unroll
    for (int p = 0; p < 4; p++)
#pragma unroll
        for (int c = 0; c < 4; c++) acc[p][c] = 0ull;

#pragma unroll 16
    for (int k = 0; k < 64; k++) {
        const ulonglong2* ap = (const ulonglong2*)(NtRs + k * NT_STRIDE + rg * 8);
        ulonglong2 A01 = ap[0];
        ulonglong2 A23 = ap[1];
        unsigned long long a[4] = {A01.x, A01.y, A23.x, A23.y};
        float4 bw = *(const float4*)(wo_s + k * 64 + cg * 4);
        unsigned long long b[4];
        PACKDUP(b[0], bw.x); PACKDUP(b[1], bw.y);
        PACKDUP(b[2], bw.z); PACKDUP(b[3], bw.w);
#pragma unroll
        for (int p = 0; p < 4; p++)
#pragma unroll
            for (int c = 0; c < 4; c++) FMA2(acc[p][c], a[p], b[c]);
    }
    __syncthreads();   // done reading Gt; region becomes Rs[128][68]

    // ---- stage results row-major ------------------------------------------
#pragma unroll
    for (int p = 0; p < 4; p++) {
        const int rA = rg * 8 + 2 * p;
        unsigned int lo0, hi0, lo1, hi1, lo2, hi2, lo3, hi3;
        UNPACK2(lo0, hi0, acc[p][0]);
        UNPACK2(lo1, hi1, acc[p][1]);
        UNPACK2(lo2, hi2, acc[p][2]);
        UNPACK2(lo3, hi3, acc[p][3]);
        *(float4*)(NtRs + rA * RS_STRIDE + cg * 4) =
            make_float4(__uint_as_float(lo0), __uint_as_float(lo1),
                        __uint_as_float(lo2), __uint_as_float(lo3));
        *(float4*)(NtRs + (rA + 1) * RS_STRIDE + cg * 4) =
            make_float4(__uint_as_float(hi0), __uint_as_float(hi1),
                        __uint_as_float(hi2), __uint_as_float(hi3));
    }
    __syncthreads();

    // ---- coalesced epilogue: out = M_raw (reread, L2-hot) + R + bo ---------
    {
        const float4* g4 = (const float4*)gbase;
        float4* o4 = (float4*)(out + ((size_t)s * R_LEN + r0) * 64);
#pragma unroll
        for (int i = 0; i < 8; i++) {
            int idx = tid + i * 256;
            int row = idx >> 4, c4 = idx & 15;
            float4 mr = g4[idx];
            float4 rr = *(const float4*)(NtRs + row * RS_STRIDE + c4 * 4);
            float4 bb = *(const float4*)(bo_s + c4 * 4);
            o4[idx] = make_float4(mr.x + rr.x + bb.x, mr.y + rr.y + bb.y,
                                  mr.z + rr.z + bb.z, mr.w + rr.w + bb.w);
        }
    }
}

// ---------------------------------------------------------------------------
extern "C" void kernel_launch(void* const* d_in, const int* in_sizes, int n_in,
                              void* d_out, int out_size)
{
    const float* M    = (const float*)d_in[0];
    const float* mask = (const float*)d_in[1];
    const float* lng  = (const float*)d_in[2];
    const float* lnb  = (const float*)d_in[3];
    const float* Wq   = (const float*)d_in[4];
    const float* Wk   = (const float*)d_in[5];
    const float* Wv   = (const float*)d_in[6];
    const float* Wg   = (const float*)d_in[7];
    const float* bg   = (const float*)d_in[8];
    const float* Wo   = (const float*)d_in[9];
    const float* bo   = (const float*)d_in[10];
    float* out = (float*)d_out;

    const size_t smem1 = (size_t)(8 * KSTR * 2 + S_LEN + NW * 128 + 64 + 64 +
                                  NW * 8 + 8 + 8 + NW) * sizeof(float);
    cudaFuncSetAttribute(attn_kernel, cudaFuncAttributeMaxDynamicSharedMemorySize,
                         (int)smem1);

    const size_t smem2 = (size_t)(8704 + 4096 + 4096 + 4 * 64) * sizeof(float);
    cudaFuncSetAttribute(out_kernel, cudaFuncAttributeMaxDynamicSharedMemorySize,
                         (int)smem2);

    attn_kernel<<<R_LEN, NTHR, smem1>>>(M, mask, lng, lnb, Wq, Wk, Wv);
    out_kernel<<<dim3(R_LEN / 128, S_LEN), 256, smem2>>>(M, lng, lnb, Wg, bg, Wo, bo, out);
}